// round 2
// baseline (speedup 1.0000x reference)
#include <cuda_runtime.h>
#include <math.h>

// ---------------------------------------------------------------------------
// SwinTransformerBlock: B=8, H=W=128, C=256, NH=8, hd=32, WS=8, SS=4
//   tokens = B*H*W = 131072, window tokens N=64, windows per image nW=256,
//   B_ = B*nW = 2048, hidden = 1024.
// Pipeline:
//   1. LN1(ref), LN1(adj) fused with cyclic shift (-4,-4) + window partition
//   2. Q = rw @ q_w + q_b ; KV = aw @ kv_w + kv_b          (SGEMM)
//   3. per-(window,head) attention: QK^T*scale + relbias + mask, softmax, @V
//   4. proj GEMM, epilogue scatters back (window reverse + shift +4,+4)
//      and adds shortcut (ref)  -> x
//   5. LN2(x) -> h1 ; fc1 (+GELU exact) ; fc2 (+x residual) -> d_out
// ---------------------------------------------------------------------------

#define MTOK 131072
#define C_DIM 256

__device__ float g_rw[MTOK * C_DIM];
__device__ float g_aw[MTOK * C_DIM];
__device__ float g_q [MTOK * C_DIM];
__device__ float g_kv[MTOK * 2 * C_DIM];
__device__ float g_ao[MTOK * C_DIM];
__device__ float g_x [MTOK * C_DIM];
__device__ float g_h1[MTOK * C_DIM];
__device__ float g_hb[MTOK * 1024];

// window-order row index -> original token index (shift by +SS with wrap)
__device__ __forceinline__ int map_row(int i) {
    int b_ = i >> 6, n = i & 63;
    int bb = b_ >> 8, wi = b_ & 255;
    int sh = ((wi >> 4) << 3) + (n >> 3);
    int sw = ((wi & 15) << 3) + (n & 7);
    int gh = (sh + 4) & 127;
    int gw = (sw + 4) & 127;
    return (bb << 14) + (gh << 7) + gw;
}

// ---------------------------------------------------------------------------
// LayerNorm kernel. GATHER: read token via map_row (shift+window partition),
// DUAL: normalize two tensors (ref & adj) sharing gamma/beta in one block.
// One block = one token, 256 threads = 256 channels.
// ---------------------------------------------------------------------------
template<bool GATHER, bool DUAL>
__global__ void ln_kernel(const float* __restrict__ x1, const float* __restrict__ x2,
                          const float* __restrict__ gam, const float* __restrict__ bet,
                          float* __restrict__ o1, float* __restrict__ o2)
{
    __shared__ float part[8][4];
    __shared__ float stats[4];
    int i = blockIdx.x;
    int c = threadIdx.x;
    size_t src = GATHER ? ((size_t)map_row(i) * C_DIM + c)
                        : ((size_t)i * C_DIM + c);
    float a = x1[src];
    float b = DUAL ? x2[src] : 0.0f;

    float v0 = a, v1 = a * a, v2 = b, v3 = b * b;
    #pragma unroll
    for (int off = 16; off; off >>= 1) {
        v0 += __shfl_down_sync(0xffffffffu, v0, off);
        v1 += __shfl_down_sync(0xffffffffu, v1, off);
        v2 += __shfl_down_sync(0xffffffffu, v2, off);
        v3 += __shfl_down_sync(0xffffffffu, v3, off);
    }
    int lane = c & 31, w = c >> 5;
    if (lane == 0) { part[w][0] = v0; part[w][1] = v1; part[w][2] = v2; part[w][3] = v3; }
    __syncthreads();
    if (c < 4) {
        float s = 0.0f;
        #pragma unroll
        for (int k = 0; k < 8; k++) s += part[k][c];
        stats[c] = s * (1.0f / 256.0f);
    }
    __syncthreads();

    float gg = gam[c], bb = bet[c];
    float m1 = stats[0];
    float var1 = stats[1] - m1 * m1;
    o1[(size_t)i * C_DIM + c] = (a - m1) * rsqrtf(var1 + 1e-5f) * gg + bb;
    if (DUAL) {
        float m2 = stats[2];
        float var2 = stats[3] - m2 * m2;
        o2[(size_t)i * C_DIM + c] = (b - m2) * rsqrtf(var2 + 1e-5f) * gg + bb;
    }
}

// ---------------------------------------------------------------------------
// SGEMM: C[M,N] = A[M,K] @ B[K,N] + bias, 128x128x8 tile, 8x8 per thread.
// MODE 0: bias only
// MODE 1: bias + exact GELU
// MODE 2: bias + scatter rows via map_row + add aux[mapped_row]   (proj)
// MODE 3: bias + add aux[row]                                     (fc2 + res)
// All dims are multiples of the tile sizes for this problem.
// ---------------------------------------------------------------------------
template<int MODE>
__global__ void __launch_bounds__(256)
sgemm_kernel(const float* __restrict__ A, const float* __restrict__ B,
             const float* __restrict__ bias, const float* __restrict__ aux,
             float* __restrict__ Cmat, int M, int N, int K)
{
    __shared__ float As[8][128];
    __shared__ float Bs[8][128];

    int tid = threadIdx.x;
    int tx = tid & 15, ty = tid >> 4;
    int rowBase = blockIdx.y << 7;
    int colBase = blockIdx.x << 7;

    int aRow = tid >> 1;
    int aCol = (tid & 1) << 2;
    int bRow = tid >> 5;
    int bCol = (tid & 31) << 2;

    const float* Ap = A + (size_t)(rowBase + aRow) * K + aCol;
    const float* Bp = B + (size_t)bRow * N + colBase + bCol;

    float acc[8][8] = {};

    for (int k0 = 0; k0 < K; k0 += 8) {
        float4 av = *(const float4*)(Ap + k0);
        float4 bv = *(const float4*)(Bp + (size_t)k0 * N);
        As[aCol + 0][aRow] = av.x;
        As[aCol + 1][aRow] = av.y;
        As[aCol + 2][aRow] = av.z;
        As[aCol + 3][aRow] = av.w;
        *(float4*)&Bs[bRow][bCol] = bv;
        __syncthreads();

        #pragma unroll
        for (int k = 0; k < 8; k++) {
            float ra[8], rb[8];
            *(float4*)(ra)     = *(const float4*)&As[k][ty * 8];
            *(float4*)(ra + 4) = *(const float4*)&As[k][ty * 8 + 4];
            *(float4*)(rb)     = *(const float4*)&Bs[k][tx * 8];
            *(float4*)(rb + 4) = *(const float4*)&Bs[k][tx * 8 + 4];
            #pragma unroll
            for (int i = 0; i < 8; i++)
                #pragma unroll
                for (int j = 0; j < 8; j++)
                    acc[i][j] += ra[i] * rb[j];
        }
        __syncthreads();
    }

    int col0 = colBase + tx * 8;
    float bz[8];
    *(float4*)(bz)     = *(const float4*)&bias[col0];
    *(float4*)(bz + 4) = *(const float4*)&bias[col0 + 4];

    #pragma unroll
    for (int i = 0; i < 8; i++) {
        int row = rowBase + ty * 8 + i;
        size_t drow = (MODE == 2) ? (size_t)map_row(row) : (size_t)row;
        float v[8];
        #pragma unroll
        for (int j = 0; j < 8; j++) {
            float t = acc[i][j] + bz[j];
            if (MODE == 1)
                t = 0.5f * t * (1.0f + erff(t * 0.70710678118654752f));
            v[j] = t;
        }
        if (MODE >= 2) {
            const float* ax = aux + drow * (size_t)N + col0;
            #pragma unroll
            for (int j = 0; j < 8; j++) v[j] += ax[j];
        }
        float* cp = Cmat + drow * (size_t)N + col0;
        *(float4*)(cp)     = *(const float4*)(v);
        *(float4*)(cp + 4) = *(const float4*)(v + 4);
    }
}

// ---------------------------------------------------------------------------
// Attention: one block per (window b_, head h). 256 threads.
// q,k,v 64x32 tiles in SMEM; scores 64x64; padding kills bank conflicts.
// ---------------------------------------------------------------------------
__global__ void __launch_bounds__(256)
attn_kernel(const float* __restrict__ Q, const float* __restrict__ KV,
            const float* __restrict__ mask, const float* __restrict__ rel,
            float* __restrict__ O)
{
    __shared__ float qs[64][32];
    __shared__ float ks[64][33];
    __shared__ float vs[64][33];
    __shared__ float sc[64][65];

    int b_ = blockIdx.x;
    int h  = blockIdx.y;
    int wi = b_ & 255;
    int tid = threadIdx.x;

    // load q, k, v tiles
    #pragma unroll
    for (int l = 0; l < 2; l++) {
        int id = tid + l * 256;           // 0..511 float4 slots
        int n = id >> 3;
        int d4 = (id & 7) << 2;
        size_t qoff = (size_t)(b_ * 64 + n) * 256 + h * 32 + d4;
        size_t koff = (size_t)(b_ * 64 + n) * 512 + h * 32 + d4;
        float4 qv = *(const float4*)&Q[qoff];
        float4 kvv = *(const float4*)&KV[koff];
        float4 vv  = *(const float4*)&KV[koff + 256];
        *(float4*)&qs[n][d4] = qv;
        ks[n][d4 + 0] = kvv.x; ks[n][d4 + 1] = kvv.y;
        ks[n][d4 + 2] = kvv.z; ks[n][d4 + 3] = kvv.w;
        vs[n][d4 + 0] = vv.x;  vs[n][d4 + 1] = vv.y;
        vs[n][d4 + 2] = vv.z;  vs[n][d4 + 3] = vv.w;
    }
    __syncthreads();

    const float scale = 0.17677669529663687f;  // 1/sqrt(32)

    // scores
    #pragma unroll
    for (int l = 0; l < 16; l++) {
        int p = tid + l * 256;            // 0..4095
        int n = p >> 6, m = p & 63;
        float s = 0.0f;
        #pragma unroll
        for (int d = 0; d < 32; d++) s += qs[n][d] * ks[m][d];
        int dr = (n >> 3) - (m >> 3) + 7;
        int dc = (n & 7) - (m & 7) + 7;
        s = s * scale + rel[(dr * 15 + dc) * 8 + h]
            + mask[((size_t)wi * 64 + n) * 64 + m];
        sc[n][m] = s;
    }
    __syncthreads();

    // softmax over rows
    if (tid < 64) {
        float mx = -1e30f;
        #pragma unroll
        for (int m = 0; m < 64; m++) mx = fmaxf(mx, sc[tid][m]);
        float sum = 0.0f;
        #pragma unroll
        for (int m = 0; m < 64; m++) {
            float e = expf(sc[tid][m] - mx);
            sc[tid][m] = e;
            sum += e;
        }
        float inv = 1.0f / sum;
        #pragma unroll
        for (int m = 0; m < 64; m++) sc[tid][m] *= inv;
    }
    __syncthreads();

    // out = attn @ v, layout (B_, N, h*32+d)
    #pragma unroll
    for (int l = 0; l < 8; l++) {
        int p = tid + l * 256;            // 0..2047
        int n = p >> 5, d = p & 31;
        float o = 0.0f;
        #pragma unroll
        for (int m = 0; m < 64; m++) o += sc[n][m] * vs[m][d];
        O[(size_t)(b_ * 64 + n) * 256 + h * 32 + d] = o;
    }
}

// ---------------------------------------------------------------------------
extern "C" void kernel_launch(void* const* d_in, const int* in_sizes, int n_in,
                              void* d_out, int out_size)
{
    const float* ref    = (const float*)d_in[0];
    const float* adj    = (const float*)d_in[1];
    const float* mask   = (const float*)d_in[2];
    // d_in[3], d_in[4] = H, W scalars (fixed 128)
    const float* n1g    = (const float*)d_in[5];
    const float* n1b    = (const float*)d_in[6];
    const float* q_w    = (const float*)d_in[7];
    const float* q_b    = (const float*)d_in[8];
    const float* kv_w   = (const float*)d_in[9];
    const float* kv_b   = (const float*)d_in[10];
    const float* rel    = (const float*)d_in[11];
    const float* proj_w = (const float*)d_in[12];
    const float* proj_b = (const float*)d_in[13];
    const float* n2g    = (const float*)d_in[14];
    const float* n2b    = (const float*)d_in[15];
    const float* fc1_w  = (const float*)d_in[16];
    const float* fc1_b  = (const float*)d_in[17];
    const float* fc2_w  = (const float*)d_in[18];
    const float* fc2_b  = (const float*)d_in[19];
    float* out = (float*)d_out;

    float *rw, *aw, *q, *kv, *ao, *x, *h1, *hb;
    cudaGetSymbolAddress((void**)&rw, g_rw);
    cudaGetSymbolAddress((void**)&aw, g_aw);
    cudaGetSymbolAddress((void**)&q,  g_q);
    cudaGetSymbolAddress((void**)&kv, g_kv);
    cudaGetSymbolAddress((void**)&ao, g_ao);
    cudaGetSymbolAddress((void**)&x,  g_x);
    cudaGetSymbolAddress((void**)&h1, g_h1);
    cudaGetSymbolAddress((void**)&hb, g_hb);

    const int M = MTOK;           // 131072 tokens
    const dim3 blk(256);

    // 1. LN1 + shift + window partition (both ref and adj)
    ln_kernel<true, true><<<M, blk>>>(ref, adj, n1g, n1b, rw, aw);

    // 2. Q and KV projections
    sgemm_kernel<0><<<dim3(2, M / 128), blk>>>(rw, q_w,  q_b,  nullptr, q,  M, 256, 256);
    sgemm_kernel<0><<<dim3(4, M / 128), blk>>>(aw, kv_w, kv_b, nullptr, kv, M, 512, 256);

    // 3. windowed attention
    attn_kernel<<<dim3(2048, 8), blk>>>(q, kv, mask, rel, ao);

    // 4. proj + window reverse + unshift + shortcut residual -> x
    sgemm_kernel<2><<<dim3(2, M / 128), blk>>>(ao, proj_w, proj_b, ref, x, M, 256, 256);

    // 5. MLP: LN2, fc1+GELU, fc2+residual -> d_out
    ln_kernel<false, false><<<M, blk>>>(x, nullptr, n2g, n2b, h1, nullptr);
    sgemm_kernel<1><<<dim3(8, M / 128), blk>>>(h1, fc1_w, fc1_b, nullptr, hb, M, 1024, 256);
    sgemm_kernel<3><<<dim3(2, M / 128), blk>>>(hb, fc2_w, fc2_b, x, out, M, 256, 1024);
}

// round 3
// speedup vs baseline: 2.0120x; 2.0120x over previous
#include <cuda_runtime.h>
#include <cuda_bf16.h>
#include <math.h>
#include <stdint.h>

// ---------------------------------------------------------------------------
// SwinTransformerBlock: B=8, H=W=128, C=256, NH=8, hd=32, WS=8, SS=4
// Round 2: all GEMMs moved to bf16 mma.sync (m16n8k16) with bf16x3 split
// (hi*hi + hi*lo + lo*hi) for fp32-class accuracy on the tensor pipe.
// ---------------------------------------------------------------------------

#define MTOK 131072
#define C_DIM 256

__device__ float g_rw[MTOK * C_DIM];
__device__ float g_aw[MTOK * C_DIM];
__device__ float g_q [MTOK * C_DIM];
__device__ float g_kv[MTOK * 2 * C_DIM];
__device__ float g_ao[MTOK * C_DIM];
__device__ float g_x [MTOK * C_DIM];
__device__ float g_h1[MTOK * C_DIM];
__device__ float g_hb[MTOK * 1024];

// window-order row index -> original token index (shift by +SS with wrap)
__device__ __forceinline__ int map_row(int i) {
    int b_ = i >> 6, n = i & 63;
    int bb = b_ >> 8, wi = b_ & 255;
    int sh = ((wi >> 4) << 3) + (n >> 3);
    int sw = ((wi & 15) << 3) + (n & 7);
    int gh = (sh + 4) & 127;
    int gw = (sw + 4) & 127;
    return (bb << 14) + (gh << 7) + gw;
}

// ---------------------------------------------------------------------------
// LayerNorm kernel (same as round 1)
// ---------------------------------------------------------------------------
template<bool GATHER, bool DUAL>
__global__ void ln_kernel(const float* __restrict__ x1, const float* __restrict__ x2,
                          const float* __restrict__ gam, const float* __restrict__ bet,
                          float* __restrict__ o1, float* __restrict__ o2)
{
    __shared__ float part[8][4];
    __shared__ float stats[4];
    int i = blockIdx.x;
    int c = threadIdx.x;
    size_t src = GATHER ? ((size_t)map_row(i) * C_DIM + c)
                        : ((size_t)i * C_DIM + c);
    float a = x1[src];
    float b = DUAL ? x2[src] : 0.0f;

    float v0 = a, v1 = a * a, v2 = b, v3 = b * b;
    #pragma unroll
    for (int off = 16; off; off >>= 1) {
        v0 += __shfl_down_sync(0xffffffffu, v0, off);
        v1 += __shfl_down_sync(0xffffffffu, v1, off);
        v2 += __shfl_down_sync(0xffffffffu, v2, off);
        v3 += __shfl_down_sync(0xffffffffu, v3, off);
    }
    int lane = c & 31, w = c >> 5;
    if (lane == 0) { part[w][0] = v0; part[w][1] = v1; part[w][2] = v2; part[w][3] = v3; }
    __syncthreads();
    if (c < 4) {
        float s = 0.0f;
        #pragma unroll
        for (int k = 0; k < 8; k++) s += part[k][c];
        stats[c] = s * (1.0f / 256.0f);
    }
    __syncthreads();

    float gg = gam[c], bb = bet[c];
    float m1 = stats[0];
    float var1 = stats[1] - m1 * m1;
    o1[(size_t)i * C_DIM + c] = (a - m1) * rsqrtf(var1 + 1e-5f) * gg + bb;
    if (DUAL) {
        float m2 = stats[2];
        float var2 = stats[3] - m2 * m2;
        o2[(size_t)i * C_DIM + c] = (b - m2) * rsqrtf(var2 + 1e-5f) * gg + bb;
    }
}

// ---------------------------------------------------------------------------
// Tensor-core GEMM (bf16x3 split): C[M,N] = A[M,K] @ B[K,N] + bias
// Block tile 128x128, K-chunk 32, 8 warps (4 Mwarp x 2 Nwarp), warp tile 32x64.
// MODE 0: bias | 1: bias+GELU | 2: bias+scatter(map_row)+aux | 3: bias+aux
// ---------------------------------------------------------------------------
__device__ __forceinline__ void ldsm4(uint32_t* r, uint32_t addr) {
    asm volatile("ldmatrix.sync.aligned.m8n8.x4.shared.b16 {%0,%1,%2,%3}, [%4];"
                 : "=r"(r[0]), "=r"(r[1]), "=r"(r[2]), "=r"(r[3]) : "r"(addr));
}
__device__ __forceinline__ void ldsm4t(uint32_t* r, uint32_t addr) {
    asm volatile("ldmatrix.sync.aligned.m8n8.x4.trans.shared.b16 {%0,%1,%2,%3}, [%4];"
                 : "=r"(r[0]), "=r"(r[1]), "=r"(r[2]), "=r"(r[3]) : "r"(addr));
}
__device__ __forceinline__ void mma_bf16(float* c, const uint32_t* a, const uint32_t* b) {
    asm volatile("mma.sync.aligned.m16n8k16.row.col.f32.bf16.bf16.f32 "
                 "{%0,%1,%2,%3}, {%4,%5,%6,%7}, {%8,%9}, {%0,%1,%2,%3};"
                 : "+f"(c[0]), "+f"(c[1]), "+f"(c[2]), "+f"(c[3])
                 : "r"(a[0]), "r"(a[1]), "r"(a[2]), "r"(a[3]), "r"(b[0]), "r"(b[1]));
}

template<int MODE>
__global__ void __launch_bounds__(256)
mma_gemm(const float* __restrict__ A, const float* __restrict__ B,
         const float* __restrict__ bias, const float* __restrict__ aux,
         float* __restrict__ Cmat, int M, int N, int K)
{
    __shared__ __align__(16) __nv_bfloat16 As[2][128][40];   // [hi/lo][m][k]
    __shared__ __align__(16) __nv_bfloat16 Bs[2][32][136];   // [hi/lo][k][n]

    int tid = threadIdx.x;
    int lane = tid & 31, wid = tid >> 5;
    int wm = wid & 3, wn = wid >> 2;
    int rowBase = blockIdx.y << 7, colBase = blockIdx.x << 7;

    float acc[2][8][4];
    #pragma unroll
    for (int i = 0; i < 2; i++)
        #pragma unroll
        for (int j = 0; j < 8; j++)
            #pragma unroll
            for (int p = 0; p < 4; p++) acc[i][j][p] = 0.0f;

    int ar = tid >> 1, ac = (tid & 1) << 4;   // A: row 0..127, col base 0/16
    int br = tid >> 3, bc = (tid & 7) << 4;   // B: row 0..31,  col base 0..112
    const float* Ap = A + (size_t)(rowBase + ar) * K + ac;
    const float* Bp = B + (size_t)br * N + colBase + bc;

    for (int k0 = 0; k0 < K; k0 += 32) {
        // stage + split A tile (128x32 fp32 -> hi/lo bf16)
        #pragma unroll
        for (int i = 0; i < 4; i++) {
            float4 v = *(const float4*)(Ap + k0 + i * 4);
            float f[4] = {v.x, v.y, v.z, v.w};
            #pragma unroll
            for (int j = 0; j < 4; j++) {
                __nv_bfloat16 h = __float2bfloat16(f[j]);
                As[0][ar][ac + i * 4 + j] = h;
                As[1][ar][ac + i * 4 + j] = __float2bfloat16(f[j] - __bfloat162float(h));
            }
        }
        // stage + split B tile (32x128 fp32 -> hi/lo bf16)
        #pragma unroll
        for (int i = 0; i < 4; i++) {
            float4 v = *(const float4*)(Bp + (size_t)k0 * N + i * 4);
            float f[4] = {v.x, v.y, v.z, v.w};
            #pragma unroll
            for (int j = 0; j < 4; j++) {
                __nv_bfloat16 h = __float2bfloat16(f[j]);
                Bs[0][br][bc + i * 4 + j] = h;
                Bs[1][br][bc + i * 4 + j] = __float2bfloat16(f[j] - __bfloat162float(h));
            }
        }
        __syncthreads();

        #pragma unroll
        for (int kk = 0; kk < 32; kk += 16) {
            uint32_t afrag[2][2][4];   // [hi/lo][im][reg]
            uint32_t bfrag[2][4][4];   // [hi/lo][n16 group][reg]
            #pragma unroll
            for (int p = 0; p < 2; p++)
                #pragma unroll
                for (int im = 0; im < 2; im++) {
                    uint32_t addr = (uint32_t)__cvta_generic_to_shared(
                        &As[p][wm * 32 + im * 16 + (lane & 15)][kk + ((lane >> 4) << 3)]);
                    ldsm4(afrag[p][im], addr);
                }
            #pragma unroll
            for (int p = 0; p < 2; p++)
                #pragma unroll
                for (int jg = 0; jg < 4; jg++) {
                    uint32_t addr = (uint32_t)__cvta_generic_to_shared(
                        &Bs[p][kk + (lane & 15)][wn * 64 + jg * 16 + ((lane >> 4) << 3)]);
                    ldsm4t(bfrag[p][jg], addr);
                }
            #pragma unroll
            for (int im = 0; im < 2; im++)
                #pragma unroll
                for (int jn = 0; jn < 8; jn++) {
                    const uint32_t* bh = &bfrag[0][jn >> 1][(jn & 1) << 1];
                    const uint32_t* bl = &bfrag[1][jn >> 1][(jn & 1) << 1];
                    mma_bf16(acc[im][jn], afrag[0][im], bh);  // hi*hi
                    mma_bf16(acc[im][jn], afrag[0][im], bl);  // hi*lo
                    mma_bf16(acc[im][jn], afrag[1][im], bh);  // lo*hi
                }
        }
        __syncthreads();
    }

    // epilogue straight from fragments
    int g = lane >> 2, t2 = (lane & 3) << 1;
    #pragma unroll
    for (int im = 0; im < 2; im++) {
        #pragma unroll
        for (int half = 0; half < 2; half++) {
            int row = rowBase + wm * 32 + im * 16 + g + half * 8;
            size_t drow = (MODE == 2) ? (size_t)map_row(row) : (size_t)row;
            #pragma unroll
            for (int jn = 0; jn < 8; jn++) {
                int col = colBase + wn * 64 + jn * 8 + t2;
                float v0 = acc[im][jn][half * 2 + 0] + bias[col];
                float v1 = acc[im][jn][half * 2 + 1] + bias[col + 1];
                if (MODE == 1) {
                    v0 = 0.5f * v0 * (1.0f + erff(v0 * 0.70710678118654752f));
                    v1 = 0.5f * v1 * (1.0f + erff(v1 * 0.70710678118654752f));
                }
                if (MODE >= 2) {
                    const float* ax = aux + drow * (size_t)N + col;
                    v0 += ax[0];
                    v1 += ax[1];
                }
                float2* cp = (float2*)(Cmat + drow * (size_t)N + col);
                *cp = make_float2(v0, v1);
            }
        }
    }
}

// ---------------------------------------------------------------------------
// Attention: one block per (window b_, head h). 256 threads. (same as round 1)
// ---------------------------------------------------------------------------
__global__ void __launch_bounds__(256)
attn_kernel(const float* __restrict__ Q, const float* __restrict__ KV,
            const float* __restrict__ mask, const float* __restrict__ rel,
            float* __restrict__ O)
{
    __shared__ float qs[64][32];
    __shared__ float ks[64][33];
    __shared__ float vs[64][33];
    __shared__ float sc[64][65];

    int b_ = blockIdx.x;
    int h  = blockIdx.y;
    int wi = b_ & 255;
    int tid = threadIdx.x;

    #pragma unroll
    for (int l = 0; l < 2; l++) {
        int id = tid + l * 256;
        int n = id >> 3;
        int d4 = (id & 7) << 2;
        size_t qoff = (size_t)(b_ * 64 + n) * 256 + h * 32 + d4;
        size_t koff = (size_t)(b_ * 64 + n) * 512 + h * 32 + d4;
        float4 qv = *(const float4*)&Q[qoff];
        float4 kvv = *(const float4*)&KV[koff];
        float4 vv  = *(const float4*)&KV[koff + 256];
        *(float4*)&qs[n][d4] = qv;
        ks[n][d4 + 0] = kvv.x; ks[n][d4 + 1] = kvv.y;
        ks[n][d4 + 2] = kvv.z; ks[n][d4 + 3] = kvv.w;
        vs[n][d4 + 0] = vv.x;  vs[n][d4 + 1] = vv.y;
        vs[n][d4 + 2] = vv.z;  vs[n][d4 + 3] = vv.w;
    }
    __syncthreads();

    const float scale = 0.17677669529663687f;  // 1/sqrt(32)

    #pragma unroll
    for (int l = 0; l < 16; l++) {
        int p = tid + l * 256;
        int n = p >> 6, m = p & 63;
        float s = 0.0f;
        #pragma unroll
        for (int d = 0; d < 32; d++) s += qs[n][d] * ks[m][d];
        int dr = (n >> 3) - (m >> 3) + 7;
        int dc = (n & 7) - (m & 7) + 7;
        s = s * scale + rel[(dr * 15 + dc) * 8 + h]
            + mask[((size_t)wi * 64 + n) * 64 + m];
        sc[n][m] = s;
    }
    __syncthreads();

    if (tid < 64) {
        float mx = -1e30f;
        #pragma unroll
        for (int m = 0; m < 64; m++) mx = fmaxf(mx, sc[tid][m]);
        float sum = 0.0f;
        #pragma unroll
        for (int m = 0; m < 64; m++) {
            float e = expf(sc[tid][m] - mx);
            sc[tid][m] = e;
            sum += e;
        }
        float inv = 1.0f / sum;
        #pragma unroll
        for (int m = 0; m < 64; m++) sc[tid][m] *= inv;
    }
    __syncthreads();

    #pragma unroll
    for (int l = 0; l < 8; l++) {
        int p = tid + l * 256;
        int n = p >> 5, d = p & 31;
        float o = 0.0f;
        #pragma unroll
        for (int m = 0; m < 64; m++) o += sc[n][m] * vs[m][d];
        O[(size_t)(b_ * 64 + n) * 256 + h * 32 + d] = o;
    }
}

// ---------------------------------------------------------------------------
extern "C" void kernel_launch(void* const* d_in, const int* in_sizes, int n_in,
                              void* d_out, int out_size)
{
    const float* ref    = (const float*)d_in[0];
    const float* adj    = (const float*)d_in[1];
    const float* mask   = (const float*)d_in[2];
    const float* n1g    = (const float*)d_in[5];
    const float* n1b    = (const float*)d_in[6];
    const float* q_w    = (const float*)d_in[7];
    const float* q_b    = (const float*)d_in[8];
    const float* kv_w   = (const float*)d_in[9];
    const float* kv_b   = (const float*)d_in[10];
    const float* rel    = (const float*)d_in[11];
    const float* proj_w = (const float*)d_in[12];
    const float* proj_b = (const float*)d_in[13];
    const float* n2g    = (const float*)d_in[14];
    const float* n2b    = (const float*)d_in[15];
    const float* fc1_w  = (const float*)d_in[16];
    const float* fc1_b  = (const float*)d_in[17];
    const float* fc2_w  = (const float*)d_in[18];
    const float* fc2_b  = (const float*)d_in[19];
    float* out = (float*)d_out;

    float *rw, *aw, *q, *kv, *ao, *x, *h1, *hb;
    cudaGetSymbolAddress((void**)&rw, g_rw);
    cudaGetSymbolAddress((void**)&aw, g_aw);
    cudaGetSymbolAddress((void**)&q,  g_q);
    cudaGetSymbolAddress((void**)&kv, g_kv);
    cudaGetSymbolAddress((void**)&ao, g_ao);
    cudaGetSymbolAddress((void**)&x,  g_x);
    cudaGetSymbolAddress((void**)&h1, g_h1);
    cudaGetSymbolAddress((void**)&hb, g_hb);

    const int M = MTOK;
    const dim3 blk(256);

    // 1. LN1 + shift + window partition (both ref and adj)
    ln_kernel<true, true><<<M, blk>>>(ref, adj, n1g, n1b, rw, aw);

    // 2. Q and KV projections (tensor core)
    mma_gemm<0><<<dim3(2, M / 128), blk>>>(rw, q_w,  q_b,  nullptr, q,  M, 256, 256);
    mma_gemm<0><<<dim3(4, M / 128), blk>>>(aw, kv_w, kv_b, nullptr, kv, M, 512, 256);

    // 3. windowed attention
    attn_kernel<<<dim3(2048, 8), blk>>>(q, kv, mask, rel, ao);

    // 4. proj + window reverse + unshift + shortcut residual -> x
    mma_gemm<2><<<dim3(2, M / 128), blk>>>(ao, proj_w, proj_b, ref, x, M, 256, 256);

    // 5. MLP: LN2, fc1+GELU, fc2+residual -> d_out
    ln_kernel<false, false><<<M, blk>>>(x, nullptr, n2g, n2b, h1, nullptr);
    mma_gemm<1><<<dim3(8, M / 128), blk>>>(h1, fc1_w, fc1_b, nullptr, hb, M, 1024, 256);
    mma_gemm<3><<<dim3(2, M / 128), blk>>>(hb, fc2_w, fc2_b, x, out, M, 256, 1024);
}

// round 5
// speedup vs baseline: 2.3459x; 1.1659x over previous
#include <cuda_runtime.h>
#include <cuda_bf16.h>
#include <math.h>
#include <stdint.h>

// ---------------------------------------------------------------------------
// SwinTransformerBlock R3: everything on tensor cores (bf16x3 split),
// producers emit pre-split hi/lo bf16, cp.async double-buffered GEMMs,
// MMA attention.  B=8, H=W=128, C=256, NH=8, hd=32, WS=8, SS=4.
// ---------------------------------------------------------------------------

typedef __nv_bfloat16 bf16;

#define MTOK 131072
#define C_DIM 256

// split weight planes (concatenated): qw[65536] kvw[131072] projw[65536]
// fc1w[262144] fc2w[262144]
#define OFF_QW    0
#define OFF_KVW   65536
#define OFF_PROJW 196608
#define OFF_FC1W  262144
#define OFF_FC2W  524288
__device__ bf16 g_wh[786432];
__device__ bf16 g_wl[786432];

__device__ bf16 g_rwh[MTOK * C_DIM], g_rwl[MTOK * C_DIM];
__device__ bf16 g_awh[MTOK * C_DIM], g_awl[MTOK * C_DIM];
__device__ bf16 g_qh [MTOK * C_DIM], g_ql [MTOK * C_DIM];
__device__ bf16 g_kvh[MTOK * 2 * C_DIM], g_kvl[MTOK * 2 * C_DIM];
__device__ bf16 g_aoh[MTOK * C_DIM], g_aol[MTOK * C_DIM];
__device__ bf16 g_h1h[MTOK * C_DIM], g_h1l[MTOK * C_DIM];
__device__ bf16 g_hbh[MTOK * 1024], g_hbl[MTOK * 1024];
__device__ float g_x[MTOK * C_DIM];

__device__ __forceinline__ int map_row(int i) {
    int b_ = i >> 6, n = i & 63;
    int bb = b_ >> 8, wi = b_ & 255;
    int sh = ((wi >> 4) << 3) + (n >> 3);
    int sw = ((wi & 15) << 3) + (n & 7);
    int gh = (sh + 4) & 127;
    int gw = (sw + 4) & 127;
    return (bb << 14) + (gh << 7) + gw;
}

__device__ __forceinline__ uint32_t smem_u32(const void* p) {
    return (uint32_t)__cvta_generic_to_shared(p);
}
__device__ __forceinline__ void ldsm4(uint32_t* r, uint32_t addr) {
    asm volatile("ldmatrix.sync.aligned.m8n8.x4.shared.b16 {%0,%1,%2,%3}, [%4];"
                 : "=r"(r[0]), "=r"(r[1]), "=r"(r[2]), "=r"(r[3]) : "r"(addr));
}
__device__ __forceinline__ void ldsm4t(uint32_t* r, uint32_t addr) {
    asm volatile("ldmatrix.sync.aligned.m8n8.x4.trans.shared.b16 {%0,%1,%2,%3}, [%4];"
                 : "=r"(r[0]), "=r"(r[1]), "=r"(r[2]), "=r"(r[3]) : "r"(addr));
}
__device__ __forceinline__ void mma_bf16(float* c, const uint32_t* a, const uint32_t* b) {
    asm volatile("mma.sync.aligned.m16n8k16.row.col.f32.bf16.bf16.f32 "
                 "{%0,%1,%2,%3}, {%4,%5,%6,%7}, {%8,%9}, {%0,%1,%2,%3};"
                 : "+f"(c[0]), "+f"(c[1]), "+f"(c[2]), "+f"(c[3])
                 : "r"(a[0]), "r"(a[1]), "r"(a[2]), "r"(a[3]), "r"(b[0]), "r"(b[1]));
}
__device__ __forceinline__ void cp16(void* dst, const void* src) {
    asm volatile("cp.async.cg.shared.global [%0], [%1], 16;"
                 :: "r"(smem_u32(dst)), "l"(src));
}
__device__ __forceinline__ void cp_commit() { asm volatile("cp.async.commit_group;"); }

__device__ __forceinline__ void split2(float v, bf16* hp, bf16* lp) {
    bf16 h = __float2bfloat16(v);
    *hp = h;
    *lp = __float2bfloat16(v - __bfloat162float(h));
}

// ---------------------------------------------------------------------------
__global__ void split_kernel(const float* __restrict__ s, bf16* __restrict__ hi,
                             bf16* __restrict__ lo, int n)
{
    for (int i = blockIdx.x * blockDim.x + threadIdx.x; i < n; i += gridDim.x * blockDim.x) {
        float v = s[i];
        bf16 h = __float2bfloat16(v);
        hi[i] = h;
        lo[i] = __float2bfloat16(v - __bfloat162float(h));
    }
}

// ---------------------------------------------------------------------------
// LayerNorm -> split bf16 outputs. GATHER: shifted-window gather. DUAL: 2 tensors.
// ---------------------------------------------------------------------------
template<bool GATHER, bool DUAL>
__global__ void ln_kernel(const float* __restrict__ x1, const float* __restrict__ x2,
                          const float* __restrict__ gam, const float* __restrict__ bet,
                          bf16* __restrict__ o1h, bf16* __restrict__ o1l,
                          bf16* __restrict__ o2h, bf16* __restrict__ o2l)
{
    __shared__ float part[8][4];
    __shared__ float stats[4];
    int i = blockIdx.x;
    int c = threadIdx.x;
    size_t src = GATHER ? ((size_t)map_row(i) * C_DIM + c) : ((size_t)i * C_DIM + c);
    float a = x1[src];
    float b = DUAL ? x2[src] : 0.0f;

    float v0 = a, v1 = a * a, v2 = b, v3 = b * b;
    #pragma unroll
    for (int off = 16; off; off >>= 1) {
        v0 += __shfl_down_sync(0xffffffffu, v0, off);
        v1 += __shfl_down_sync(0xffffffffu, v1, off);
        v2 += __shfl_down_sync(0xffffffffu, v2, off);
        v3 += __shfl_down_sync(0xffffffffu, v3, off);
    }
    int lane = c & 31, w = c >> 5;
    if (lane == 0) { part[w][0] = v0; part[w][1] = v1; part[w][2] = v2; part[w][3] = v3; }
    __syncthreads();
    if (c < 4) {
        float s = 0.0f;
        #pragma unroll
        for (int k = 0; k < 8; k++) s += part[k][c];
        stats[c] = s * (1.0f / 256.0f);
    }
    __syncthreads();

    float gg = gam[c], bb = bet[c];
    float m1 = stats[0];
    float r1 = rsqrtf(stats[1] - m1 * m1 + 1e-5f);
    size_t di = (size_t)i * C_DIM + c;
    split2((a - m1) * r1 * gg + bb, o1h + di, o1l + di);
    if (DUAL) {
        float m2 = stats[2];
        float r2 = rsqrtf(stats[3] - m2 * m2 + 1e-5f);
        split2((b - m2) * r2 * gg + bb, o2h + di, o2l + di);
    }
}

// ---------------------------------------------------------------------------
// Tensor-core GEMM, pre-split bf16 inputs, cp.async 2-stage pipeline.
// Block 128x128, K-chunk 16. 8 warps (4 Mwarp x 2 Nwarp), warp tile 32x64.
// MODE 0: bias -> split out | 1: bias+GELU -> split out
// MODE 2: bias + scatter(map_row) + aux -> fp32 | 3: bias + aux -> fp32
// ---------------------------------------------------------------------------
#define AS_IDX(st,p,r,c) ((((st)*2+(p))*128 + (r))*24 + (c))
#define BS_IDX(st,p,r,c) ((((st)*2+(p))*16  + (r))*136 + (c))

template<int MODE>
__global__ void __launch_bounds__(256)
mma_gemm(const bf16* __restrict__ Ah, const bf16* __restrict__ Al,
         const bf16* __restrict__ Bh, const bf16* __restrict__ Bl,
         const float* __restrict__ bias, const float* __restrict__ aux,
         bf16* __restrict__ Ch, bf16* __restrict__ Cl, float* __restrict__ Cf,
         int M, int N, int K)
{
    __shared__ __align__(16) bf16 As[2 * 2 * 128 * 24];   // [st][p][128][16+8pad]
    __shared__ __align__(16) bf16 Bs[2 * 2 * 16 * 136];   // [st][p][16][128+8pad]

    int tid = threadIdx.x;
    int lane = tid & 31, wid = tid >> 5;
    int wm = wid & 3, wn = wid >> 2;
    int rowBase = blockIdx.y << 7, colBase = blockIdx.x << 7;

    float acc[2][8][4];
    #pragma unroll
    for (int i = 0; i < 2; i++)
        #pragma unroll
        for (int j = 0; j < 8; j++)
            #pragma unroll
            for (int p = 0; p < 4; p++) acc[i][j][p] = 0.0f;

    int nK = K >> 4;

    // stage loader: 512 A-chunks + 512 B-chunks of 16B each, 4 per thread
    auto stage_load = [&](int st, int k0) {
        #pragma unroll
        for (int l = 0; l < 2; l++) {
            int id = tid + l * 256;           // 0..511
            int p = id >> 8, rem = id & 255;
            int r = rem >> 1, c8 = (rem & 1) << 3;
            const bf16* src = (p ? Al : Ah) + (size_t)(rowBase + r) * K + k0 + c8;
            cp16(&As[AS_IDX(st, p, r, c8)], src);
        }
        #pragma unroll
        for (int l = 0; l < 2; l++) {
            int id = tid + l * 256;
            int p = id >> 8, rem = id & 255;
            int r = rem >> 4, c8 = (rem & 15) << 3;
            const bf16* src = (p ? Bl : Bh) + (size_t)(k0 + r) * N + colBase + c8;
            cp16(&Bs[BS_IDX(st, p, r, c8)], src);
        }
    };

    stage_load(0, 0);
    cp_commit();

    for (int kt = 0; kt < nK; kt++) {
        if (kt + 1 < nK) {
            stage_load((kt + 1) & 1, (kt + 1) << 4);
            cp_commit();
            asm volatile("cp.async.wait_group 1;");
        } else {
            asm volatile("cp.async.wait_group 0;");
        }
        __syncthreads();

        int s = kt & 1;
        uint32_t af[2][2][4];
        #pragma unroll
        for (int p = 0; p < 2; p++)
            #pragma unroll
            for (int im = 0; im < 2; im++)
                ldsm4(af[p][im], smem_u32(&As[AS_IDX(s, p, wm * 32 + im * 16 + (lane & 15),
                                                     (lane >> 4) << 3)]));
        uint32_t bfr[2][4][4];
        #pragma unroll
        for (int p = 0; p < 2; p++)
            #pragma unroll
            for (int jg = 0; jg < 4; jg++)
                ldsm4t(bfr[p][jg], smem_u32(&Bs[BS_IDX(s, p, lane & 15,
                                                       wn * 64 + jg * 16 + ((lane >> 4) << 3))]));
        #pragma unroll
        for (int im = 0; im < 2; im++)
            #pragma unroll
            for (int jn = 0; jn < 8; jn++) {
                const uint32_t* bh = &bfr[0][jn >> 1][(jn & 1) << 1];
                const uint32_t* bl = &bfr[1][jn >> 1][(jn & 1) << 1];
                mma_bf16(acc[im][jn], af[0][im], bh);
                mma_bf16(acc[im][jn], af[0][im], bl);
                mma_bf16(acc[im][jn], af[1][im], bh);
            }
        __syncthreads();
    }

    // epilogue
    int g = lane >> 2, t2 = (lane & 3) << 1;
    #pragma unroll
    for (int im = 0; im < 2; im++) {
        #pragma unroll
        for (int half = 0; half < 2; half++) {
            int row = rowBase + wm * 32 + im * 16 + g + half * 8;
            size_t drow = (MODE == 2) ? (size_t)map_row(row) : (size_t)row;
            #pragma unroll
            for (int jn = 0; jn < 8; jn++) {
                int col = colBase + wn * 64 + jn * 8 + t2;
                float v0 = acc[im][jn][half * 2 + 0] + bias[col];
                float v1 = acc[im][jn][half * 2 + 1] + bias[col + 1];
                if (MODE == 1) {
                    v0 = 0.5f * v0 * (1.0f + erff(v0 * 0.70710678118654752f));
                    v1 = 0.5f * v1 * (1.0f + erff(v1 * 0.70710678118654752f));
                }
                if (MODE <= 1) {
                    bf16 h0 = __float2bfloat16(v0);
                    bf16 h1 = __float2bfloat16(v1);
                    __nv_bfloat162 th, tl;
                    th.x = h0; th.y = h1;
                    tl.x = __float2bfloat16(v0 - __bfloat162float(h0));
                    tl.y = __float2bfloat16(v1 - __bfloat162float(h1));
                    *(__nv_bfloat162*)(Ch + drow * (size_t)N + col) = th;
                    *(__nv_bfloat162*)(Cl + drow * (size_t)N + col) = tl;
                } else {
                    const float* ax = aux + drow * (size_t)N + col;
                    v0 += ax[0];
                    v1 += ax[1];
                    *(float2*)(Cf + drow * (size_t)N + col) = make_float2(v0, v1);
                }
            }
        }
    }
}

// ---------------------------------------------------------------------------
// MMA attention: one block per (window, head), 256 threads (8 warps).
// Scores via bf16x3 mma (Q row-major A, K [n][k] as col-major B), fp32 softmax,
// P split hi/lo, PV via bf16x3 mma (V trans-loaded). SMEM regions overlap in
// time: {qs,ks} die before {sc,ps} are born; vs lives throughout.
// ---------------------------------------------------------------------------
#define SM_QS 0          // [2][64][40] bf16  = 10240 B
#define SM_KS 10240      // [2][64][40] bf16  = 10240 B
#define SM_SC 0          // [64][68]  fp32    = 17408 B (overlays qs+ks head)
#define SM_PS 17408      // [2][64][72] bf16  = 18432 B (overlays ks tail)
#define SM_VS 35840      // [2][64][40] bf16  = 10240 B
#define SM_TOTAL 46080

__global__ void __launch_bounds__(256)
attn_kernel(const bf16* __restrict__ Qh, const bf16* __restrict__ Ql,
            const bf16* __restrict__ KVh, const bf16* __restrict__ KVl,
            const float* __restrict__ mask, const float* __restrict__ rel,
            bf16* __restrict__ Oh, bf16* __restrict__ Ol)
{
    __shared__ __align__(16) char sm[SM_TOTAL];
    bf16*  qs = (bf16*)(sm + SM_QS);
    bf16*  ks = (bf16*)(sm + SM_KS);
    float* sc = (float*)(sm + SM_SC);
    bf16*  ps = (bf16*)(sm + SM_PS);
    bf16*  vs = (bf16*)(sm + SM_VS);

    int b_ = blockIdx.x, h = blockIdx.y, wi = b_ & 255;
    int tid = threadIdx.x, lane = tid & 31, wid = tid >> 5;
    int wm = wid & 3, wn = wid >> 2;

    // load q,k,v hi/lo tiles: 1536 16B chunks, 6 per thread
    #pragma unroll
    for (int l = 0; l < 6; l++) {
        int id = tid + l * 256;
        int tsr = id >> 9;                // 0 q, 1 k, 2 v
        int rem = id & 511;
        int p = rem >> 8, r2 = rem & 255;
        int r = r2 >> 2, c8 = (r2 & 3) << 3;
        const bf16* gsrc;
        bf16* dst;
        if (tsr == 0) {
            gsrc = (p ? Ql : Qh) + (size_t)(b_ * 64 + r) * 256 + h * 32 + c8;
            dst = qs + (p * 64 + r) * 40 + c8;
        } else if (tsr == 1) {
            gsrc = (p ? KVl : KVh) + (size_t)(b_ * 64 + r) * 512 + h * 32 + c8;
            dst = ks + (p * 64 + r) * 40 + c8;
        } else {
            gsrc = (p ? KVl : KVh) + (size_t)(b_ * 64 + r) * 512 + 256 + h * 32 + c8;
            dst = vs + (p * 64 + r) * 40 + c8;
        }
        *(float4*)dst = *(const float4*)gsrc;
    }
    __syncthreads();

    // ---- scores: S = Q K^T (bf16x3)
    float accS[4][4];
    #pragma unroll
    for (int j = 0; j < 4; j++)
        #pragma unroll
        for (int p = 0; p < 4; p++) accS[j][p] = 0.0f;

    #pragma unroll
    for (int kk = 0; kk < 32; kk += 16) {
        uint32_t ah[4], al[4];
        ldsm4(ah, smem_u32(qs + (0 * 64 + wm * 16 + (lane & 15)) * 40 + kk + ((lane >> 4) << 3)));
        ldsm4(al, smem_u32(qs + (1 * 64 + wm * 16 + (lane & 15)) * 40 + kk + ((lane >> 4) << 3)));
        #pragma unroll
        for (int jg = 0; jg < 2; jg++) {
            int nrow = wn * 32 + jg * 16 + ((lane >> 4) << 3) + (lane & 7);
            int kcol = kk + (((lane >> 3) & 1) << 3);
            uint32_t bh[4], bl[4];
            ldsm4(bh, smem_u32(ks + (0 * 64 + nrow) * 40 + kcol));
            ldsm4(bl, smem_u32(ks + (1 * 64 + nrow) * 40 + kcol));
            #pragma unroll
            for (int t = 0; t < 2; t++) {
                mma_bf16(accS[jg * 2 + t], ah, bh + t * 2);
                mma_bf16(accS[jg * 2 + t], ah, bl + t * 2);
                mma_bf16(accS[jg * 2 + t], al, bh + t * 2);
            }
        }
    }
    __syncthreads();   // qs/ks dead; sc region now writable

    const float scale = 0.17677669529663687f;
    int g = lane >> 2, t2 = (lane & 3) << 1;
    #pragma unroll
    for (int jn = 0; jn < 4; jn++) {
        int col = wn * 32 + jn * 8 + t2;
        #pragma unroll
        for (int half = 0; half < 2; half++) {
            int n = wm * 16 + g + half * 8;
            #pragma unroll
            for (int u = 0; u < 2; u++) {
                int m = col + u;
                int dr = (n >> 3) - (m >> 3) + 7;
                int dc = (n & 7) - (m & 7) + 7;
                float v = accS[jn][half * 2 + u] * scale
                          + rel[(dr * 15 + dc) * 8 + h]
                          + mask[(size_t)wi * 4096 + n * 64 + m];
                sc[n * 68 + m] = v;
            }
        }
    }
    __syncthreads();

    // ---- softmax (4 threads per row) + split to ps
    {
        int row = tid >> 2, p = tid & 3;
        float e[16];
        float mx = -1e30f;
        #pragma unroll
        for (int j = 0; j < 16; j++) {
            e[j] = sc[row * 68 + p * 16 + j];
            mx = fmaxf(mx, e[j]);
        }
        mx = fmaxf(mx, __shfl_xor_sync(0xffffffffu, mx, 1));
        mx = fmaxf(mx, __shfl_xor_sync(0xffffffffu, mx, 2));
        float s = 0.0f;
        #pragma unroll
        for (int j = 0; j < 16; j++) { e[j] = __expf(e[j] - mx); s += e[j]; }
        s += __shfl_xor_sync(0xffffffffu, s, 1);
        s += __shfl_xor_sync(0xffffffffu, s, 2);
        float inv = 1.0f / s;
        #pragma unroll
        for (int j = 0; j < 16; j++) {
            float pv = e[j] * inv;
            bf16 hh = __float2bfloat16(pv);
            ps[(0 * 64 + row) * 72 + p * 16 + j] = hh;
            ps[(1 * 64 + row) * 72 + p * 16 + j] =
                __float2bfloat16(pv - __bfloat162float(hh));
        }
    }
    __syncthreads();

    // ---- out = P V (bf16x3)
    float accO[2][4];
    #pragma unroll
    for (int t = 0; t < 2; t++)
        #pragma unroll
        for (int p = 0; p < 4; p++) accO[t][p] = 0.0f;

    #pragma unroll
    for (int kk = 0; kk < 64; kk += 16) {
        uint32_t ah[4], al[4];
        ldsm4(ah, smem_u32(ps + (0 * 64 + wm * 16 + (lane & 15)) * 72 + kk + ((lane >> 4) << 3)));
        ldsm4(al, smem_u32(ps + (1 * 64 + wm * 16 + (lane & 15)) * 72 + kk + ((lane >> 4) << 3)));
        uint32_t bh[4], bl[4];
        ldsm4t(bh, smem_u32(vs + (0 * 64 + kk + (lane & 15)) * 40 + wn * 16 + ((lane >> 4) << 3)));
        ldsm4t(bl, smem_u32(vs + (1 * 64 + kk + (lane & 15)) * 40 + wn * 16 + ((lane >> 4) << 3)));
        #pragma unroll
        for (int t = 0; t < 2; t++) {
            mma_bf16(accO[t], ah, bh + t * 2);
            mma_bf16(accO[t], ah, bl + t * 2);
            mma_bf16(accO[t], al, bh + t * 2);
        }
    }

    #pragma unroll
    for (int t = 0; t < 2; t++) {
        int col = h * 32 + wn * 16 + t * 8 + t2;
        #pragma unroll
        for (int half = 0; half < 2; half++) {
            size_t row = (size_t)b_ * 64 + wm * 16 + g + half * 8;
            float v0 = accO[t][half * 2 + 0];
            float v1 = accO[t][half * 2 + 1];
            bf16 h0 = __float2bfloat16(v0);
            bf16 h1 = __float2bfloat16(v1);
            __nv_bfloat162 th, tl;
            th.x = h0; th.y = h1;
            tl.x = __float2bfloat16(v0 - __bfloat162float(h0));
            tl.y = __float2bfloat16(v1 - __bfloat162float(h1));
            *(__nv_bfloat162*)(Oh + row * 256 + col) = th;
            *(__nv_bfloat162*)(Ol + row * 256 + col) = tl;
        }
    }
}

// ---------------------------------------------------------------------------
extern "C" void kernel_launch(void* const* d_in, const int* in_sizes, int n_in,
                              void* d_out, int out_size)
{
    const float* ref    = (const float*)d_in[0];
    const float* adj    = (const float*)d_in[1];
    const float* mask   = (const float*)d_in[2];
    const float* n1g    = (const float*)d_in[5];
    const float* n1b    = (const float*)d_in[6];
    const float* q_w    = (const float*)d_in[7];
    const float* q_b    = (const float*)d_in[8];
    const float* kv_w   = (const float*)d_in[9];
    const float* kv_b   = (const float*)d_in[10];
    const float* rel    = (const float*)d_in[11];
    const float* proj_w = (const float*)d_in[12];
    const float* proj_b = (const float*)d_in[13];
    const float* n2g    = (const float*)d_in[14];
    const float* n2b    = (const float*)d_in[15];
    const float* fc1_w  = (const float*)d_in[16];
    const float* fc1_b  = (const float*)d_in[17];
    const float* fc2_w  = (const float*)d_in[18];
    const float* fc2_b  = (const float*)d_in[19];
    float* out = (float*)d_out;

    bf16 *wh, *wl, *rwh, *rwl, *awh, *awl, *qh, *ql, *kvh, *kvl;
    bf16 *aoh, *aol, *h1h, *h1l, *hbh, *hbl;
    float* x;
    cudaGetSymbolAddress((void**)&wh,  g_wh);
    cudaGetSymbolAddress((void**)&wl,  g_wl);
    cudaGetSymbolAddress((void**)&rwh, g_rwh);
    cudaGetSymbolAddress((void**)&rwl, g_rwl);
    cudaGetSymbolAddress((void**)&awh, g_awh);
    cudaGetSymbolAddress((void**)&awl, g_awl);
    cudaGetSymbolAddress((void**)&qh,  g_qh);
    cudaGetSymbolAddress((void**)&ql,  g_ql);
    cudaGetSymbolAddress((void**)&kvh, g_kvh);
    cudaGetSymbolAddress((void**)&kvl, g_kvl);
    cudaGetSymbolAddress((void**)&aoh, g_aoh);
    cudaGetSymbolAddress((void**)&aol, g_aol);
    cudaGetSymbolAddress((void**)&h1h, g_h1h);
    cudaGetSymbolAddress((void**)&h1l, g_h1l);
    cudaGetSymbolAddress((void**)&hbh, g_hbh);
    cudaGetSymbolAddress((void**)&hbl, g_hbl);
    cudaGetSymbolAddress((void**)&x,   g_x);

    const int M = MTOK;
    const dim3 blk(256);

    // 0. split weights hi/lo (cheap, every launch for determinism)
    split_kernel<<<128, 256>>>(q_w,    wh + OFF_QW,    wl + OFF_QW,    65536);
    split_kernel<<<256, 256>>>(kv_w,   wh + OFF_KVW,   wl + OFF_KVW,   131072);
    split_kernel<<<128, 256>>>(proj_w, wh + OFF_PROJW, wl + OFF_PROJW, 65536);
    split_kernel<<<512, 256>>>(fc1_w,  wh + OFF_FC1W,  wl + OFF_FC1W,  262144);
    split_kernel<<<512, 256>>>(fc2_w,  wh + OFF_FC2W,  wl + OFF_FC2W,  262144);

    // 1. LN1 + shift + window partition -> split bf16
    ln_kernel<true, true><<<M, blk>>>(ref, adj, n1g, n1b, rwh, rwl, awh, awl);

    // 2. Q and KV projections -> split bf16
    mma_gemm<0><<<dim3(2, M / 128), blk>>>(rwh, rwl, wh + OFF_QW, wl + OFF_QW,
                                           q_b, nullptr, qh, ql, nullptr, M, 256, 256);
    mma_gemm<0><<<dim3(4, M / 128), blk>>>(awh, awl, wh + OFF_KVW, wl + OFF_KVW,
                                           kv_b, nullptr, kvh, kvl, nullptr, M, 512, 256);

    // 3. windowed attention (tensor core) -> split bf16
    attn_kernel<<<dim3(2048, 8), blk>>>(qh, ql, kvh, kvl, mask, rel, aoh, aol);

    // 4. proj + window reverse + unshift + shortcut -> fp32 x
    mma_gemm<2><<<dim3(2, M / 128), blk>>>(aoh, aol, wh + OFF_PROJW, wl + OFF_PROJW,
                                           proj_b, ref, nullptr, nullptr, x, M, 256, 256);

    // 5. MLP
    ln_kernel<false, false><<<M, blk>>>(x, nullptr, n2g, n2b, h1h, h1l, nullptr, nullptr);
    mma_gemm<1><<<dim3(8, M / 128), blk>>>(h1h, h1l, wh + OFF_FC1W, wl + OFF_FC1W,
                                           fc1_b, nullptr, hbh, hbl, nullptr, M, 1024, 256);
    mma_gemm<3><<<dim3(2, M / 128), blk>>>(hbh, hbl, wh + OFF_FC2W, wl + OFF_FC2W,
                                           fc2_b, x, nullptr, nullptr, out, M, 256, 1024);
}

// round 10
// speedup vs baseline: 4.9448x; 2.1078x over previous
#include <cuda_runtime.h>
#include <cuda_fp16.h>
#include <math.h>
#include <stdint.h>

// ---------------------------------------------------------------------------
// SwinTransformerBlock R5: single-fp16 tensor-core datapath (fp32 accumulate,
// fp32 residual stream / softmax / LN stats). 3x fewer MMAs, 2x less traffic
// than the bf16x3 scheme. B=8, H=W=128, C=256, NH=8, hd=32, WS=8, SS=4.
// ---------------------------------------------------------------------------

typedef __half hf;

#define MTOK 131072
#define C_DIM 256

// fp16 weight planes (concatenated)
#define OFF_QW    0
#define OFF_KVW   65536
#define OFF_PROJW 196608
#define OFF_FC1W  262144
#define OFF_FC2W  524288
__device__ hf g_w[786432];

__device__ hf g_rw[MTOK * C_DIM];
__device__ hf g_aw[MTOK * C_DIM];
__device__ hf g_q [MTOK * C_DIM];
__device__ hf g_kv[MTOK * 2 * C_DIM];
__device__ hf g_ao[MTOK * C_DIM];
__device__ hf g_h1[MTOK * C_DIM];
__device__ hf g_hb[MTOK * 1024];
__device__ float g_x[MTOK * C_DIM];

__device__ __forceinline__ int map_row(int i) {
    int b_ = i >> 6, n = i & 63;
    int bb = b_ >> 8, wi = b_ & 255;
    int sh = ((wi >> 4) << 3) + (n >> 3);
    int sw = ((wi & 15) << 3) + (n & 7);
    int gh = (sh + 4) & 127;
    int gw = (sw + 4) & 127;
    return (bb << 14) + (gh << 7) + gw;
}

__device__ __forceinline__ uint32_t smem_u32(const void* p) {
    return (uint32_t)__cvta_generic_to_shared(p);
}
__device__ __forceinline__ void ldsm4(uint32_t* r, uint32_t addr) {
    asm volatile("ldmatrix.sync.aligned.m8n8.x4.shared.b16 {%0,%1,%2,%3}, [%4];"
                 : "=r"(r[0]), "=r"(r[1]), "=r"(r[2]), "=r"(r[3]) : "r"(addr));
}
__device__ __forceinline__ void ldsm4t(uint32_t* r, uint32_t addr) {
    asm volatile("ldmatrix.sync.aligned.m8n8.x4.trans.shared.b16 {%0,%1,%2,%3}, [%4];"
                 : "=r"(r[0]), "=r"(r[1]), "=r"(r[2]), "=r"(r[3]) : "r"(addr));
}
__device__ __forceinline__ void mma_f16(float* c, const uint32_t* a, const uint32_t* b) {
    asm volatile("mma.sync.aligned.m16n8k16.row.col.f32.f16.f16.f32 "
                 "{%0,%1,%2,%3}, {%4,%5,%6,%7}, {%8,%9}, {%0,%1,%2,%3};"
                 : "+f"(c[0]), "+f"(c[1]), "+f"(c[2]), "+f"(c[3])
                 : "r"(a[0]), "r"(a[1]), "r"(a[2]), "r"(a[3]), "r"(b[0]), "r"(b[1]));
}
__device__ __forceinline__ void cp16(void* dst, const void* src) {
    asm volatile("cp.async.cg.shared.global [%0], [%1], 16;"
                 :: "r"(smem_u32(dst)), "l"(src));
}
__device__ __forceinline__ void cp_commit() { asm volatile("cp.async.commit_group;"); }

// ---------------------------------------------------------------------------
__global__ void cvt_kernel(const float* __restrict__ s, hf* __restrict__ d, int n)
{
    for (int i = blockIdx.x * blockDim.x + threadIdx.x; i < n; i += gridDim.x * blockDim.x)
        d[i] = __float2half(s[i]);
}

// ---------------------------------------------------------------------------
// LayerNorm: one warp per token, 8 tokens per block. float4 I/O, fp16 out.
// ---------------------------------------------------------------------------
template<bool GATHER, bool DUAL>
__global__ void __launch_bounds__(256)
ln_kernel(const float* __restrict__ x1, const float* __restrict__ x2,
          const float* __restrict__ gam, const float* __restrict__ bet,
          hf* __restrict__ o1, hf* __restrict__ o2)
{
    int lane = threadIdx.x & 31, wid = threadIdx.x >> 5;
    int i = (blockIdx.x << 3) + wid;
    size_t base = (size_t)(GATHER ? map_row(i) : i) * C_DIM + (lane << 3);

    float a[8], b[8];
    *(float4*)(a)     = *(const float4*)&x1[base];
    *(float4*)(a + 4) = *(const float4*)&x1[base + 4];
    if (DUAL) {
        *(float4*)(b)     = *(const float4*)&x2[base];
        *(float4*)(b + 4) = *(const float4*)&x2[base + 4];
    }

    float s0 = 0, s1 = 0, s2 = 0, s3 = 0;
    #pragma unroll
    for (int j = 0; j < 8; j++) {
        s0 += a[j]; s1 += a[j] * a[j];
        if (DUAL) { s2 += b[j]; s3 += b[j] * b[j]; }
    }
    #pragma unroll
    for (int off = 16; off; off >>= 1) {
        s0 += __shfl_xor_sync(0xffffffffu, s0, off);
        s1 += __shfl_xor_sync(0xffffffffu, s1, off);
        if (DUAL) {
            s2 += __shfl_xor_sync(0xffffffffu, s2, off);
            s3 += __shfl_xor_sync(0xffffffffu, s3, off);
        }
    }
    float m1 = s0 * (1.0f / 256.0f);
    float r1 = rsqrtf(s1 * (1.0f / 256.0f) - m1 * m1 + 1e-5f);

    float g[8], bt[8];
    *(float4*)(g)      = *(const float4*)&gam[lane << 3];
    *(float4*)(g + 4)  = *(const float4*)&gam[(lane << 3) + 4];
    *(float4*)(bt)     = *(const float4*)&bet[lane << 3];
    *(float4*)(bt + 4) = *(const float4*)&bet[(lane << 3) + 4];

    size_t dst = (size_t)i * C_DIM + (lane << 3);
    hf t[8];
    #pragma unroll
    for (int j = 0; j < 8; j++) t[j] = __float2half((a[j] - m1) * r1 * g[j] + bt[j]);
    *(float4*)&o1[dst] = *(float4*)t;
    if (DUAL) {
        float m2 = s2 * (1.0f / 256.0f);
        float r2 = rsqrtf(s3 * (1.0f / 256.0f) - m2 * m2 + 1e-5f);
        #pragma unroll
        for (int j = 0; j < 8; j++) t[j] = __float2half((b[j] - m2) * r2 * g[j] + bt[j]);
        *(float4*)&o2[dst] = *(float4*)t;
    }
}

// ---------------------------------------------------------------------------
// fp16 tensor-core GEMM: C[M,N] = A[M,K] @ B[K,N] + bias.
// Block 128x128, K-chunk 32, 2-stage cp.async. 8 warps, warp tile 32x64.
// MODE 0: bias -> fp16 | 1: bias+GELU -> fp16
// MODE 2: bias+scatter(map_row)+aux -> fp32 | 3: bias+aux -> fp32
// ---------------------------------------------------------------------------
#define AS_IDX(st,r,c) ((((st) << 7) + (r)) * 40 + (c))
#define BS_IDX(st,r,c) ((((st) << 5) + (r)) * 136 + (c))

template<int MODE>
__global__ void __launch_bounds__(256)
mma_gemm(const hf* __restrict__ Ah, const hf* __restrict__ Bh,
         const float* __restrict__ bias, const float* __restrict__ aux,
         hf* __restrict__ Chf, float* __restrict__ Cf,
         int M, int N, int K)
{
    __shared__ __align__(16) hf As[2 * 128 * 40];   // 20480 B
    __shared__ __align__(16) hf Bs[2 * 32 * 136];   // 17408 B

    int tid = threadIdx.x;
    int lane = tid & 31, wid = tid >> 5;
    int wm = wid & 3, wn = wid >> 2;
    int rowBase = blockIdx.y << 7, colBase = blockIdx.x << 7;

    float acc[2][8][4];
    #pragma unroll
    for (int i = 0; i < 2; i++)
        #pragma unroll
        for (int j = 0; j < 8; j++)
            #pragma unroll
            for (int p = 0; p < 4; p++) acc[i][j][p] = 0.0f;

    int nK = K >> 5;

    auto stage_load = [&](int st, int k0) {
        #pragma unroll
        for (int l = 0; l < 2; l++) {
            int id = tid + (l << 8);                 // 0..511
            int r = id >> 2, c8 = (id & 3) << 3;
            cp16(&As[AS_IDX(st, r, c8)], Ah + (size_t)(rowBase + r) * K + k0 + c8);
        }
        #pragma unroll
        for (int l = 0; l < 2; l++) {
            int id = tid + (l << 8);
            int r = id >> 4, c8 = (id & 15) << 3;
            cp16(&Bs[BS_IDX(st, r, c8)], Bh + (size_t)(k0 + r) * N + colBase + c8);
        }
    };

    stage_load(0, 0);
    cp_commit();

    for (int kt = 0; kt < nK; kt++) {
        if (kt + 1 < nK) {
            stage_load((kt + 1) & 1, (kt + 1) << 5);
            cp_commit();
            asm volatile("cp.async.wait_group 1;");
        } else {
            asm volatile("cp.async.wait_group 0;");
        }
        __syncthreads();

        int s = kt & 1;
        #pragma unroll
        for (int kk = 0; kk < 32; kk += 16) {
            uint32_t af[2][4];
            #pragma unroll
            for (int im = 0; im < 2; im++)
                ldsm4(af[im], smem_u32(&As[AS_IDX(s, wm * 32 + im * 16 + (lane & 15),
                                                  kk + ((lane >> 4) << 3))]));
            uint32_t bfr[4][4];
            #pragma unroll
            for (int jg = 0; jg < 4; jg++)
                ldsm4t(bfr[jg], smem_u32(&Bs[BS_IDX(s, kk + (lane & 15),
                                                    wn * 64 + jg * 16 + ((lane >> 4) << 3))]));
            #pragma unroll
            for (int im = 0; im < 2; im++)
                #pragma unroll
                for (int jn = 0; jn < 8; jn++)
                    mma_f16(acc[im][jn], af[im], &bfr[jn >> 1][(jn & 1) << 1]);
        }
        __syncthreads();
    }

    // epilogue
    int g = lane >> 2, t2 = (lane & 3) << 1;
    #pragma unroll
    for (int im = 0; im < 2; im++) {
        #pragma unroll
        for (int half_ = 0; half_ < 2; half_++) {
            int row = rowBase + wm * 32 + im * 16 + g + half_ * 8;
            size_t drow = (MODE == 2) ? (size_t)map_row(row) : (size_t)row;
            #pragma unroll
            for (int jn = 0; jn < 8; jn++) {
                int col = colBase + wn * 64 + jn * 8 + t2;
                float v0 = acc[im][jn][half_ * 2 + 0] + bias[col];
                float v1 = acc[im][jn][half_ * 2 + 1] + bias[col + 1];
                if (MODE == 1) {
                    v0 = 0.5f * v0 * (1.0f + erff(v0 * 0.70710678118654752f));
                    v1 = 0.5f * v1 * (1.0f + erff(v1 * 0.70710678118654752f));
                }
                if (MODE <= 1) {
                    __half2 t;
                    t.x = __float2half(v0);
                    t.y = __float2half(v1);
                    *(__half2*)(Chf + drow * (size_t)N + col) = t;
                } else {
                    const float* ax = aux + drow * (size_t)N + col;
                    *(float2*)(Cf + drow * (size_t)N + col) =
                        make_float2(v0 + ax[0], v1 + ax[1]);
                }
            }
        }
    }
}

// ---------------------------------------------------------------------------
// fp16 MMA attention: one block per (window, head), 256 threads (8 warps).
// ---------------------------------------------------------------------------
__global__ void __launch_bounds__(256)
attn_kernel(const hf* __restrict__ Q, const hf* __restrict__ KV,
            const float* __restrict__ mask, const float* __restrict__ rel,
            hf* __restrict__ O)
{
    __shared__ __align__(16) hf qs[64 * 40];
    __shared__ __align__(16) hf ks[64 * 40];
    __shared__ __align__(16) hf vs[64 * 40];
    __shared__ __align__(16) float sc[64 * 68];
    __shared__ __align__(16) hf ps[64 * 72];

    int b_ = blockIdx.x, h = blockIdx.y, wi = b_ & 255;
    int tid = threadIdx.x, lane = tid & 31, wid = tid >> 5;
    int wm = wid & 3, wn = wid >> 2;

    // load q,k,v tiles: 768 16B chunks, 3 per thread
    #pragma unroll
    for (int l = 0; l < 3; l++) {
        int id = tid + (l << 8);
        int tsr = id >> 8;
        int rem = id & 255;
        int r = rem >> 2, c8 = (rem & 3) << 3;
        const hf* gsrc;
        hf* dst;
        if (tsr == 0) { gsrc = Q  + (size_t)(b_ * 64 + r) * 256 + h * 32 + c8;       dst = qs + r * 40 + c8; }
        else if (tsr == 1) { gsrc = KV + (size_t)(b_ * 64 + r) * 512 + h * 32 + c8;  dst = ks + r * 40 + c8; }
        else { gsrc = KV + (size_t)(b_ * 64 + r) * 512 + 256 + h * 32 + c8;          dst = vs + r * 40 + c8; }
        *(float4*)dst = *(const float4*)gsrc;
    }
    __syncthreads();

    // ---- S = Q K^T
    float accS[4][4];
    #pragma unroll
    for (int j = 0; j < 4; j++)
        #pragma unroll
        for (int p = 0; p < 4; p++) accS[j][p] = 0.0f;

    #pragma unroll
    for (int kk = 0; kk < 32; kk += 16) {
        uint32_t ah[4];
        ldsm4(ah, smem_u32(qs + (wm * 16 + (lane & 15)) * 40 + kk + ((lane >> 4) << 3)));
        #pragma unroll
        for (int jg = 0; jg < 2; jg++) {
            int nrow = wn * 32 + jg * 16 + ((lane >> 4) << 3) + (lane & 7);
            int kcol = kk + (((lane >> 3) & 1) << 3);
            uint32_t bh[4];
            ldsm4(bh, smem_u32(ks + nrow * 40 + kcol));
            #pragma unroll
            for (int t = 0; t < 2; t++)
                mma_f16(accS[jg * 2 + t], ah, bh + t * 2);
        }
    }

    const float scale = 0.17677669529663687f;
    int g = lane >> 2, t2 = (lane & 3) << 1;
    #pragma unroll
    for (int jn = 0; jn < 4; jn++) {
        int col = wn * 32 + jn * 8 + t2;
        #pragma unroll
        for (int half_ = 0; half_ < 2; half_++) {
            int n = wm * 16 + g + half_ * 8;
            #pragma unroll
            for (int u = 0; u < 2; u++) {
                int m = col + u;
                int dr = (n >> 3) - (m >> 3) + 7;
                int dc = (n & 7) - (m & 7) + 7;
                sc[n * 68 + m] = accS[jn][half_ * 2 + u] * scale
                                 + rel[(dr * 15 + dc) * 8 + h]
                                 + mask[(size_t)wi * 4096 + n * 64 + m];
            }
        }
    }
    __syncthreads();

    // ---- softmax (4 threads per row)
    {
        int row = tid >> 2, p = tid & 3;
        float e[16];
        float mx = -1e30f;
        #pragma unroll
        for (int j = 0; j < 16; j++) {
            e[j] = sc[row * 68 + p * 16 + j];
            mx = fmaxf(mx, e[j]);
        }
        mx = fmaxf(mx, __shfl_xor_sync(0xffffffffu, mx, 1));
        mx = fmaxf(mx, __shfl_xor_sync(0xffffffffu, mx, 2));
        float s = 0.0f;
        #pragma unroll
        for (int j = 0; j < 16; j++) { e[j] = __expf(e[j] - mx); s += e[j]; }
        s += __shfl_xor_sync(0xffffffffu, s, 1);
        s += __shfl_xor_sync(0xffffffffu, s, 2);
        float inv = 1.0f / s;
        hf t[16];
        #pragma unroll
        for (int j = 0; j < 16; j++) t[j] = __float2half(e[j] * inv);
        #pragma unroll
        for (int j = 0; j < 16; j += 8)
            *(float4*)&ps[row * 72 + p * 16 + j] = *(float4*)&t[j];
    }
    __syncthreads();

    // ---- out = P V
    float accO[2][4];
    #pragma unroll
    for (int t = 0; t < 2; t++)
        #pragma unroll
        for (int p = 0; p < 4; p++) accO[t][p] = 0.0f;

    #pragma unroll
    for (int kk = 0; kk < 64; kk += 16) {
        uint32_t ah[4];
        ldsm4(ah, smem_u32(ps + (wm * 16 + (lane & 15)) * 72 + kk + ((lane >> 4) << 3)));
        uint32_t bh[4];
        ldsm4t(bh, smem_u32(vs + (kk + (lane & 15)) * 40 + wn * 16 + ((lane >> 4) << 3)));
        #pragma unroll
        for (int t = 0; t < 2; t++)
            mma_f16(accO[t], ah, bh + t * 2);
    }

    #pragma unroll
    for (int t = 0; t < 2; t++) {
        int col = h * 32 + wn * 16 + t * 8 + t2;
        #pragma unroll
        for (int half_ = 0; half_ < 2; half_++) {
            size_t row = (size_t)b_ * 64 + wm * 16 + g + half_ * 8;
            __half2 o;
            o.x = __float2half(accO[t][half_ * 2 + 0]);
            o.y = __float2half(accO[t][half_ * 2 + 1]);
            *(__half2*)(O + row * 256 + col) = o;
        }
    }
}

// ---------------------------------------------------------------------------
extern "C" void kernel_launch(void* const* d_in, const int* in_sizes, int n_in,
                              void* d_out, int out_size)
{
    const float* ref    = (const float*)d_in[0];
    const float* adj    = (const float*)d_in[1];
    const float* mask   = (const float*)d_in[2];
    const float* n1g    = (const float*)d_in[5];
    const float* n1b    = (const float*)d_in[6];
    const float* q_w    = (const float*)d_in[7];
    const float* q_b    = (const float*)d_in[8];
    const float* kv_w   = (const float*)d_in[9];
    const float* kv_b   = (const float*)d_in[10];
    const float* rel    = (const float*)d_in[11];
    const float* proj_w = (const float*)d_in[12];
    const float* proj_b = (const float*)d_in[13];
    const float* n2g    = (const float*)d_in[14];
    const float* n2b    = (const float*)d_in[15];
    const float* fc1_w  = (const float*)d_in[16];
    const float* fc1_b  = (const float*)d_in[17];
    const float* fc2_w  = (const float*)d_in[18];
    const float* fc2_b  = (const float*)d_in[19];
    float* out = (float*)d_out;

    hf *w, *rw, *aw, *q, *kv, *ao, *h1, *hb;
    float* x;
    cudaGetSymbolAddress((void**)&w,  g_w);
    cudaGetSymbolAddress((void**)&rw, g_rw);
    cudaGetSymbolAddress((void**)&aw, g_aw);
    cudaGetSymbolAddress((void**)&q,  g_q);
    cudaGetSymbolAddress((void**)&kv, g_kv);
    cudaGetSymbolAddress((void**)&ao, g_ao);
    cudaGetSymbolAddress((void**)&h1, g_h1);
    cudaGetSymbolAddress((void**)&hb, g_hb);
    cudaGetSymbolAddress((void**)&x,  g_x);

    const int M = MTOK;
    const dim3 blk(256);

    // 0. weights -> fp16
    cvt_kernel<<<64, 256>>>(q_w,    w + OFF_QW,    65536);
    cvt_kernel<<<128, 256>>>(kv_w,  w + OFF_KVW,   131072);
    cvt_kernel<<<64, 256>>>(proj_w, w + OFF_PROJW, 65536);
    cvt_kernel<<<256, 256>>>(fc1_w, w + OFF_FC1W,  262144);
    cvt_kernel<<<256, 256>>>(fc2_w, w + OFF_FC2W,  262144);

    // 1. LN1 + shift + window partition
    ln_kernel<true, true><<<M / 8, blk>>>(ref, adj, n1g, n1b, rw, aw);

    // 2. Q and KV projections
    mma_gemm<0><<<dim3(2, M / 128), blk>>>(rw, w + OFF_QW,  q_b,  nullptr, q,  nullptr, M, 256, 256);
    mma_gemm<0><<<dim3(4, M / 128), blk>>>(aw, w + OFF_KVW, kv_b, nullptr, kv, nullptr, M, 512, 256);

    // 3. windowed attention
    attn_kernel<<<dim3(2048, 8), blk>>>(q, kv, mask, rel, ao);

    // 4. proj + window reverse + unshift + shortcut -> fp32 x
    mma_gemm<2><<<dim3(2, M / 128), blk>>>(ao, w + OFF_PROJW, proj_b, ref, nullptr, x, M, 256, 256);

    // 5. MLP
    ln_kernel<false, false><<<M / 8, blk>>>(x, nullptr, n2g, n2b, h1, nullptr);
    mma_gemm<1><<<dim3(8, M / 128), blk>>>(h1, w + OFF_FC1W, fc1_b, nullptr, hb, nullptr, M, 1024, 256);
    mma_gemm<3><<<dim3(2, M / 128), blk>>>(hb, w + OFF_FC2W, fc2_b, x, nullptr, out, M, 256, 1024);
}